// round 11
// baseline (speedup 1.0000x reference)
#include <cuda_runtime.h>

// Fused depthwise conv: y = gauss_valid(fd_valid(x)) == one 13-tap valid FIR.
// Composed kernel is SYMMETRIC: out[j] = sum_{k<6} w[k]*(x[j+k]+x[j+12-k])
//                                        + w[6]*x[j+6].
//
// x: [8,4,T] f32 -> 32 rows, T = 1048576. out rows: Tout = T-12.
//
// R9: R8 (persistent, 6 CTAs/SM, GROUPS=2 front-batched coalesced LDG.128,
// int32 + shift/mask addressing, symmetric weights) + streaming cache
// policy: __ldcs on input (evict-first; halo reuse is immediate), __stcs on
// output (write-once, don't retain in L2).

#define BLOCK  256
#define GROUPS 2
#define GTILE  (BLOCK * 4)        // 1024 outputs per group
#define TILE   (GTILE * GROUPS)   // 2048 outputs per tile
#define TPR_LOG2 9                // tilesPerRow = 512 (for T=2^20)

__global__ __launch_bounds__(BLOCK, 6)
void fused_fir13_cs(const float* __restrict__ x,
                    const float* __restrict__ fd,   // 5 taps
                    const float* __restrict__ gk,   // 9 taps
                    float* __restrict__ out,
                    int T, int Tout, int tilesTotal)
{
    __shared__ float wsh[7];
    const int tid = threadIdx.x;

    // Compose symmetric half-kernel once per CTA.
    if (tid < 7) {
        float acc = 0.f;
        const int hi = tid < 4 ? tid : 4;
        for (int i = 0; i <= hi; ++i) acc += fd[i] * gk[tid - i];
        wsh[tid] = acc;
    }
    __syncthreads();

    float w[7];
    #pragma unroll
    for (int k = 0; k < 7; ++k) w[k] = wsh[k];

    for (int t = blockIdx.x; t < tilesTotal; t += gridDim.x) {
        const int row  = t >> TPR_LOG2;                 // block-uniform
        const int tile = t & ((1 << TPR_LOG2) - 1);
        const int xb   = row * T;                       // int32 (max ~33.5M)
        const int ob   = row * Tout;
        const int start = tile * TILE;

        // ---- Front-batch all loads: 8 coalesced LDG.128.CS in flight ----
        float r[GROUPS][16];
        #pragma unroll
        for (int q = 0; q < GROUPS; ++q) {
            const int gb = start + q * GTILE + tid * 4;
            if (gb + 16 <= T) {
                #pragma unroll
                for (int v = 0; v < 4; ++v) {
                    float4 f = __ldcs((const float4*)(x + xb + gb + 4 * v));
                    r[q][4*v+0] = f.x; r[q][4*v+1] = f.y;
                    r[q][4*v+2] = f.z; r[q][4*v+3] = f.w;
                }
            } else {
                #pragma unroll
                for (int i = 0; i < 16; ++i) {
                    const int gi = gb + i;
                    r[q][i] = (gi < T) ? __ldcs(x + xb + gi) : 0.f;
                }
            }
        }

        // ---- Compute + store per group (streaming stores) ----
        #pragma unroll
        for (int q = 0; q < GROUPS; ++q) {
            const int gb = start + q * GTILE + tid * 4;
            float a[4];
            #pragma unroll
            for (int j = 0; j < 4; ++j) {
                float acc = w[6] * r[q][j + 6];
                #pragma unroll
                for (int k = 0; k < 6; ++k)
                    acc = fmaf(w[k], r[q][j + k] + r[q][j + 12 - k], acc);
                a[j] = acc;
            }
            if (gb + 4 <= Tout) {
                __stcs((float4*)(out + ob + gb),
                       make_float4(a[0], a[1], a[2], a[3]));
            } else {
                #pragma unroll
                for (int v = 0; v < 4; ++v)
                    if (gb + v < Tout) __stcs(out + ob + gb + v, a[v]);
            }
        }
    }
}

extern "C" void kernel_launch(void* const* d_in, const int* in_sizes, int n_in,
                              void* d_out, int out_size)
{
    const float* x  = (const float*)d_in[0];
    const float* fd = (const float*)d_in[1];   // 5 elements
    const float* gk = (const float*)d_in[2];   // 9 elements
    float* out = (float*)d_out;

    const int ROWS = 32;                       // 8 * 4
    const int T    = in_sizes[0] / ROWS;       // 1048576
    const int Tout = T - 12;                   // 1048564

    const int tilesPerRow = 1 << TPR_LOG2;              // 512
    const int tilesTotal  = ROWS * tilesPerRow;         // 16384

    const int SMS = 148, CTAS_PER_SM = 6;
    int blocks = SMS * CTAS_PER_SM;                     // 888 persistent CTAs
    if (blocks > tilesTotal) blocks = tilesTotal;

    fused_fir13_cs<<<blocks, BLOCK>>>(x, fd, gk, out, T, Tout, tilesTotal);
}